// round 7
// baseline (speedup 1.0000x reference)
#include <cuda_runtime.h>
#include <cstdint>
#include <math.h>

// Problem constants (from reference: T=8192, H=1024, I=2816, E=8, top_k=2)
#define T_TOK 8192
#define H_DIM 1024
#define I_DIM 2816
#define E_NUM 8
#define TOPK  2
#define MAXROWS (T_TOK * TOPK)   // 16384 token-expert rows total

#define N1T 44   // GEMM1 n-tiles: I/64 (each block produces 64 h-columns)
#define N2T 8    // GEMM2 n-tiles: H/128
#define MAXMT 136                 // sum_e ceil(cnt_e/128) <= 135
#define GRID1 (MAXMT * N1T)       // 5984
#define GRID2 (MAXMT * N2T)       // 1088

// ---------------- scratch (device globals: allocation-free) ----------------
__device__ float g_h[(size_t)MAXROWS * I_DIM];   // compacted silu(gate)*up, ~184.5 MB
__device__ int   g_tok[E_NUM * T_TOK];
__device__ float g_wt [E_NUM * T_TOK];
__device__ int   g_cnt[E_NUM];
__device__ int   g_rowbase[E_NUM];
__device__ int   g_cum1[E_NUM + 1];
__device__ int   g_cum2[E_NUM + 1];

// ---------------- helpers ----------------
__device__ __forceinline__ float tf32r(float x) {
    uint32_t u;
    asm("cvt.rna.tf32.f32 %0, %1;" : "=r"(u) : "f"(x));
    return __uint_as_float(u);
}

__device__ __forceinline__ void mma_tf32(float (&d)[4], const uint32_t (&a)[4],
                                         const uint32_t (&b)[2]) {
    asm volatile(
        "mma.sync.aligned.m16n8k8.row.col.f32.tf32.tf32.f32 "
        "{%0,%1,%2,%3}, {%4,%5,%6,%7}, {%8,%9}, {%0,%1,%2,%3};\n"
        : "+f"(d[0]), "+f"(d[1]), "+f"(d[2]), "+f"(d[3])
        : "r"(a[0]), "r"(a[1]), "r"(a[2]), "r"(a[3]), "r"(b[0]), "r"(b[1]));
}

// ---------------- phase 0: init ----------------
__global__ void init_kernel() {
    if (threadIdx.x < E_NUM) g_cnt[threadIdx.x] = 0;
}

// ---------------- phase 1: router (softmax -> top2 -> renorm -> scatter) ----
__global__ void router_kernel(const float* __restrict__ logits) {
    int t = blockIdx.x * blockDim.x + threadIdx.x;
    if (t >= T_TOK) return;
    float l[E_NUM];
#pragma unroll
    for (int e = 0; e < E_NUM; e++) l[e] = logits[t * E_NUM + e];
    int b0 = 0;
#pragma unroll
    for (int e = 1; e < E_NUM; e++) if (l[e] > l[b0]) b0 = e;
    int b1 = (b0 == 0) ? 1 : 0;
#pragma unroll
    for (int e = 0; e < E_NUM; e++) if (e != b0 && l[e] > l[b1]) b1 = e;
    // renormalized top-2 weights: softmax denominator cancels
    float r  = expf(l[b1] - l[b0]);           // p1/p0, <= 1
    float w0 = 1.0f / (1.0f + r);
    float w1 = r / (1.0f + r);
    int s0 = atomicAdd(&g_cnt[b0], 1);
    g_tok[b0 * T_TOK + s0] = t;  g_wt[b0 * T_TOK + s0] = w0;
    int s1 = atomicAdd(&g_cnt[b1], 1);
    g_tok[b1 * T_TOK + s1] = t;  g_wt[b1 * T_TOK + s1] = w1;
}

// ---------------- phase 2: tile scheduling prefix sums ----------------
__global__ void sched_kernel() {
    int base = 0, t1 = 0, t2 = 0;
    g_cum1[0] = 0; g_cum2[0] = 0;
    for (int e = 0; e < E_NUM; e++) {
        g_rowbase[e] = base;
        int c = g_cnt[e];
        base += c;
        int mt = (c + 127) >> 7;
        t1 += mt * N1T; g_cum1[e + 1] = t1;
        t2 += mt * N2T; g_cum2[e + 1] = t2;
    }
}

// ---------------- phase 3: GEMM1  h = silu(x W1^T) * (x W3^T) ----------------
// Block tile: 128 gathered token rows x 128 interleaved (gate,up) columns, K=H.
// B-tile row j (j=2*jj+s): s=0 -> w13[e, nt*64+jj, :], s=1 -> w13[e, I+nt*64+jj, :]
// => each thread's mma (c0,c1) pair = (gate,up) of the same h column.
__global__ __launch_bounds__(256) void gemm1_kernel(const float* __restrict__ x,
                                                    const float* __restrict__ w13) {
    __shared__ float As[128 * 20];
    __shared__ float Bs[128 * 20];

    int bid = blockIdx.x;
    if (bid >= g_cum1[E_NUM]) return;
    int e = 0;
#pragma unroll
    for (int k = 0; k < E_NUM; k++) if (bid >= g_cum1[k + 1]) e = k + 1;
    int local = bid - g_cum1[e];
    int mt = local / N1T, nt = local - mt * N1T;   // nt fastest -> L2 A reuse
    int cnt  = g_cnt[e];
    int rowb = g_rowbase[e];

    int tid  = threadIdx.x;
    int lane = tid & 31, wid = tid >> 5;
    int wm = wid >> 1, wn = wid & 1;

    // global load assignment: thread owns one (row, 8-col half) of each tile
    int arow  = tid >> 1;            // 0..127
    int halfc = (tid & 1) * 8;
    int slot  = mt * 128 + arow;
    const float* aptr = nullptr;
    if (slot < cnt) {
        int tok = g_tok[e * T_TOK + slot];
        aptr = x + (size_t)tok * H_DIM + halfc;
    }
    int jj = arow >> 1, s = arow & 1;
    const float* bptr = w13 + ((size_t)e * 2 * I_DIM + (s ? I_DIM : 0) +
                               (size_t)nt * 64 + jj) * H_DIM + halfc;

    float acc[2][8][4];
#pragma unroll
    for (int i = 0; i < 2; i++)
#pragma unroll
        for (int j = 0; j < 8; j++)
#pragma unroll
            for (int c = 0; c < 4; c++) acc[i][j][c] = 0.0f;

    int sb = arow * 20 + halfc;
    for (int kb = 0; kb < H_DIM / 16; kb++) {
        int k0 = kb * 16;
        float4 av0 = make_float4(0, 0, 0, 0), av1 = make_float4(0, 0, 0, 0);
        if (aptr) {
            av0 = *(const float4*)(aptr + k0);
            av1 = *(const float4*)(aptr + k0 + 4);
        }
        float4 bv0 = *(const float4*)(bptr + k0);
        float4 bv1 = *(const float4*)(bptr + k0 + 4);
        __syncthreads();
        As[sb + 0] = tf32r(av0.x); As[sb + 1] = tf32r(av0.y);
        As[sb + 2] = tf32r(av0.z); As[sb + 3] = tf32r(av0.w);
        As[sb + 4] = tf32r(av1.x); As[sb + 5] = tf32r(av1.y);
        As[sb + 6] = tf32r(av1.z); As[sb + 7] = tf32r(av1.w);
        Bs[sb + 0] = tf32r(bv0.x); Bs[sb + 1] = tf32r(bv0.y);
        Bs[sb + 2] = tf32r(bv0.z); Bs[sb + 3] = tf32r(bv0.w);
        Bs[sb + 4] = tf32r(bv1.x); Bs[sb + 5] = tf32r(bv1.y);
        Bs[sb + 6] = tf32r(bv1.z); Bs[sb + 7] = tf32r(bv1.w);
        __syncthreads();

        const uint32_t* Au = (const uint32_t*)As;
        const uint32_t* Bu = (const uint32_t*)Bs;
        int lr = lane >> 2, lc = lane & 3;
#pragma unroll
        for (int kst = 0; kst < 2; kst++) {
            int kc = kst * 8 + lc;
            uint32_t a[2][4], b[8][2];
#pragma unroll
            for (int m2 = 0; m2 < 2; m2++) {
                int r = wm * 32 + m2 * 16 + lr;
                a[m2][0] = Au[r * 20 + kc];
                a[m2][1] = Au[(r + 8) * 20 + kc];
                a[m2][2] = Au[r * 20 + kc + 4];
                a[m2][3] = Au[(r + 8) * 20 + kc + 4];
            }
#pragma unroll
            for (int n8 = 0; n8 < 8; n8++) {
                int c = wn * 64 + n8 * 8 + lr;
                b[n8][0] = Bu[c * 20 + kc];
                b[n8][1] = Bu[c * 20 + kc + 4];
            }
#pragma unroll
            for (int m2 = 0; m2 < 2; m2++)
#pragma unroll
                for (int n8 = 0; n8 < 8; n8++) mma_tf32(acc[m2][n8], a[m2], b[n8]);
        }
    }

    // epilogue: h = silu(gate) * up
    int lr = lane >> 2, q = lane & 3;
#pragma unroll
    for (int m2 = 0; m2 < 2; m2++) {
        int r0 = wm * 32 + m2 * 16 + lr;
        int slot0 = mt * 128 + r0;
        int slot1 = slot0 + 8;
#pragma unroll
        for (int n8 = 0; n8 < 8; n8++) {
            int hcol = nt * 64 + wn * 32 + n8 * 4 + q;
            if (slot0 < cnt) {
                float g = acc[m2][n8][0], u = acc[m2][n8][1];
                g_h[(size_t)(rowb + slot0) * I_DIM + hcol] = g / (1.0f + expf(-g)) * u;
            }
            if (slot1 < cnt) {
                float g = acc[m2][n8][2], u = acc[m2][n8][3];
                g_h[(size_t)(rowb + slot1) * I_DIM + hcol] = g / (1.0f + expf(-g)) * u;
            }
        }
    }
}

// ---------------- phase 4: GEMM2  out += wgt * (h W2^T) ----------------
__global__ __launch_bounds__(256) void gemm2_kernel(const float* __restrict__ w2,
                                                    float* __restrict__ out) {
    __shared__ float As[128 * 20];
    __shared__ float Bs[128 * 20];

    int bid = blockIdx.x;
    if (bid >= g_cum2[E_NUM]) return;
    int e = 0;
#pragma unroll
    for (int k = 0; k < E_NUM; k++) if (bid >= g_cum2[k + 1]) e = k + 1;
    int local = bid - g_cum2[e];
    int mt = local >> 3, nt = local & 7;   // nt fastest -> L2 reuse of h tile
    int cnt  = g_cnt[e];
    int rowb = g_rowbase[e];

    int tid  = threadIdx.x;
    int lane = tid & 31, wid = tid >> 5;
    int wm = wid >> 1, wn = wid & 1;

    int arow  = tid >> 1;
    int halfc = (tid & 1) * 8;
    int slot  = mt * 128 + arow;
    const float* aptr = (slot < cnt)
        ? g_h + (size_t)(rowb + slot) * I_DIM + halfc : nullptr;
    const float* bptr = w2 + ((size_t)e * H_DIM + nt * 128 + arow) * I_DIM + halfc;

    float acc[2][8][4];
#pragma unroll
    for (int i = 0; i < 2; i++)
#pragma unroll
        for (int j = 0; j < 8; j++)
#pragma unroll
            for (int c = 0; c < 4; c++) acc[i][j][c] = 0.0f;

    int sb = arow * 20 + halfc;
    for (int kb = 0; kb < I_DIM / 16; kb++) {
        int k0 = kb * 16;
        float4 av0 = make_float4(0, 0, 0, 0), av1 = make_float4(0, 0, 0, 0);
        if (aptr) {
            av0 = *(const float4*)(aptr + k0);
            av1 = *(const float4*)(aptr + k0 + 4);
        }
        float4 bv0 = *(const float4*)(bptr + k0);
        float4 bv1 = *(const float4*)(bptr + k0 + 4);
        __syncthreads();
        As[sb + 0] = tf32r(av0.x); As[sb + 1] = tf32r(av0.y);
        As[sb + 2] = tf32r(av0.z); As[sb + 3] = tf32r(av0.w);
        As[sb + 4] = tf32r(av1.x); As[sb + 5] = tf32r(av1.y);
        As[sb + 6] = tf32r(av1.z); As[sb + 7] = tf32r(av1.w);
        Bs[sb + 0] = tf32r(bv0.x); Bs[sb + 1] = tf32r(bv0.y);
        Bs[sb + 2] = tf32r(bv0.z); Bs[sb + 3] = tf32r(bv0.w);
        Bs[sb + 4] = tf32r(bv1.x); Bs[sb + 5] = tf32r(bv1.y);
        Bs[sb + 6] = tf32r(bv1.z); Bs[sb + 7] = tf32r(bv1.w);
        __syncthreads();

        const uint32_t* Au = (const uint32_t*)As;
        const uint32_t* Bu = (const uint32_t*)Bs;
        int lr = lane >> 2, lc = lane & 3;
#pragma unroll
        for (int kst = 0; kst < 2; kst++) {
            int kc = kst * 8 + lc;
            uint32_t a[2][4], b[8][2];
#pragma unroll
            for (int m2 = 0; m2 < 2; m2++) {
                int r = wm * 32 + m2 * 16 + lr;
                a[m2][0] = Au[r * 20 + kc];
                a[m2][1] = Au[(r + 8) * 20 + kc];
                a[m2][2] = Au[r * 20 + kc + 4];
                a[m2][3] = Au[(r + 8) * 20 + kc + 4];
            }
#pragma unroll
            for (int n8 = 0; n8 < 8; n8++) {
                int c = wn * 64 + n8 * 8 + lr;
                b[n8][0] = Bu[c * 20 + kc];
                b[n8][1] = Bu[c * 20 + kc + 4];
            }
#pragma unroll
            for (int m2 = 0; m2 < 2; m2++)
#pragma unroll
                for (int n8 = 0; n8 < 8; n8++) mma_tf32(acc[m2][n8], a[m2], b[n8]);
        }
    }

    // epilogue: weighted atomic combine (each out element gets exactly 2 adds)
    int lr = lane >> 2, q = lane & 3;
#pragma unroll
    for (int m2 = 0; m2 < 2; m2++) {
        int slot0 = mt * 128 + wm * 32 + m2 * 16 + lr;
        int slot1 = slot0 + 8;
        int   tok0 = 0, tok1 = 0;
        float wt0 = 0.0f, wt1 = 0.0f;
        if (slot0 < cnt) { tok0 = g_tok[e * T_TOK + slot0]; wt0 = g_wt[e * T_TOK + slot0]; }
        if (slot1 < cnt) { tok1 = g_tok[e * T_TOK + slot1]; wt1 = g_wt[e * T_TOK + slot1]; }
#pragma unroll
        for (int n8 = 0; n8 < 8; n8++) {
            int col = nt * 128 + wn * 64 + n8 * 8 + q * 2;
            if (slot0 < cnt) {
                atomicAdd(out + (size_t)tok0 * H_DIM + col,     acc[m2][n8][0] * wt0);
                atomicAdd(out + (size_t)tok0 * H_DIM + col + 1, acc[m2][n8][1] * wt0);
            }
            if (slot1 < cnt) {
                atomicAdd(out + (size_t)tok1 * H_DIM + col,     acc[m2][n8][2] * wt1);
                atomicAdd(out + (size_t)tok1 * H_DIM + col + 1, acc[m2][n8][3] * wt1);
            }
        }
    }
}

// ---------------- launch ----------------
extern "C" void kernel_launch(void* const* d_in, const int* in_sizes, int n_in,
                              void* d_out, int out_size) {
    const float* x      = (const float*)d_in[0];
    const float* logits = (const float*)d_in[1];
    const float* w13    = (const float*)d_in[2];
    const float* w2     = (const float*)d_in[3];
    float* out = (float*)d_out;

    cudaMemsetAsync(out, 0, (size_t)T_TOK * H_DIM * sizeof(float));
    init_kernel<<<1, 32>>>();
    router_kernel<<<T_TOK / 256, 256>>>(logits);
    sched_kernel<<<1, 1>>>();
    gemm1_kernel<<<GRID1, 256>>>(x, w13);
    gemm2_kernel<<<GRID2, 256>>>(w2, out);
}

// round 9
// speedup vs baseline: 1.0034x; 1.0034x over previous
#include <cuda_runtime.h>
#include <cstdint>
#include <math.h>

// Problem constants (from reference: T=8192, H=1024, I=2816, E=8, top_k=2)
#define T_TOK 8192
#define H_DIM 1024
#define I_DIM 2816
#define E_NUM 8
#define TOPK  2
#define MAXROWS (T_TOK * TOPK)   // 16384 token-expert rows total

#define N1T 44   // GEMM1 n-tiles: I/64 (each block produces 64 h-columns)
#define N2T 8    // GEMM2 n-tiles: H/128
#define MAXMT 136                 // sum_e ceil(cnt_e/128) <= 135
#define GRID1 (MAXMT * N1T)       // 5984
#define GRID2 (MAXMT * N2T)       // 1088

// ---------------- scratch (device globals: allocation-free) ----------------
__device__ float g_h[(size_t)MAXROWS * I_DIM];   // compacted silu(gate)*up, ~184.5 MB
__device__ int   g_tok[E_NUM * T_TOK];
__device__ float g_wt [E_NUM * T_TOK];
__device__ int   g_cnt[E_NUM];
__device__ int   g_rowbase[E_NUM];
__device__ int   g_cum1[E_NUM + 1];
__device__ int   g_cum2[E_NUM + 1];

// ---------------- helpers ----------------
__device__ __forceinline__ float tf32r(float x) {
    uint32_t u;
    asm("cvt.rna.tf32.f32 %0, %1;" : "=r"(u) : "f"(x));
    return __uint_as_float(u);
}

__device__ __forceinline__ void mma_tf32(float (&d)[4], const uint32_t (&a)[4],
                                         const uint32_t (&b)[2]) {
    asm volatile(
        "mma.sync.aligned.m16n8k8.row.col.f32.tf32.tf32.f32 "
        "{%0,%1,%2,%3}, {%4,%5,%6,%7}, {%8,%9}, {%0,%1,%2,%3};\n"
        : "+f"(d[0]), "+f"(d[1]), "+f"(d[2]), "+f"(d[3])
        : "r"(a[0]), "r"(a[1]), "r"(a[2]), "r"(a[3]), "r"(b[0]), "r"(b[1]));
}

// ---------------- phase 0: init ----------------
__global__ void init_kernel() {
    if (threadIdx.x < E_NUM) g_cnt[threadIdx.x] = 0;
}

// ---------------- phase 1: router (softmax -> top2 -> renorm -> scatter) ----
__global__ void router_kernel(const float* __restrict__ logits) {
    int t = blockIdx.x * blockDim.x + threadIdx.x;
    if (t >= T_TOK) return;
    float l[E_NUM];
#pragma unroll
    for (int e = 0; e < E_NUM; e++) l[e] = logits[t * E_NUM + e];
    int b0 = 0;
#pragma unroll
    for (int e = 1; e < E_NUM; e++) if (l[e] > l[b0]) b0 = e;
    int b1 = (b0 == 0) ? 1 : 0;
#pragma unroll
    for (int e = 0; e < E_NUM; e++) if (e != b0 && l[e] > l[b1]) b1 = e;
    // renormalized top-2 weights: softmax denominator cancels
    float r  = expf(l[b1] - l[b0]);           // p1/p0, <= 1
    float w0 = 1.0f / (1.0f + r);
    float w1 = r / (1.0f + r);
    int s0 = atomicAdd(&g_cnt[b0], 1);
    g_tok[b0 * T_TOK + s0] = t;  g_wt[b0 * T_TOK + s0] = w0;
    int s1 = atomicAdd(&g_cnt[b1], 1);
    g_tok[b1 * T_TOK + s1] = t;  g_wt[b1 * T_TOK + s1] = w1;
}

// ---------------- phase 2: tile scheduling prefix sums ----------------
__global__ void sched_kernel() {
    int base = 0, t1 = 0, t2 = 0;
    g_cum1[0] = 0; g_cum2[0] = 0;
    for (int e = 0; e < E_NUM; e++) {
        g_rowbase[e] = base;
        int c = g_cnt[e];
        base += c;
        int mt = (c + 127) >> 7;
        t1 += mt * N1T; g_cum1[e + 1] = t1;
        t2 += mt * N2T; g_cum2[e + 1] = t2;
    }
}

// ---------------- phase 3: GEMM1  h = silu(x W1^T) * (x W3^T) ----------------
// Block tile: 128 gathered token rows x 128 interleaved (gate,up) columns, K=H.
// B-tile row j (j=2*jj+s): s=0 -> w13[e, nt*64+jj, :], s=1 -> w13[e, I+nt*64+jj, :]
// => each thread's mma (c0,c1) pair = (gate,up) of the same h column.
__global__ __launch_bounds__(256) void gemm1_kernel(const float* __restrict__ x,
                                                    const float* __restrict__ w13) {
    __shared__ float As[128 * 20];
    __shared__ float Bs[128 * 20];

    int bid = blockIdx.x;
    if (bid >= g_cum1[E_NUM]) return;
    int e = 0;
#pragma unroll
    for (int k = 0; k < E_NUM; k++) if (bid >= g_cum1[k + 1]) e = k + 1;
    int local = bid - g_cum1[e];
    int mt = local / N1T, nt = local - mt * N1T;   // nt fastest -> L2 A reuse
    int cnt  = g_cnt[e];
    int rowb = g_rowbase[e];

    int tid  = threadIdx.x;
    int lane = tid & 31, wid = tid >> 5;
    int wm = wid >> 1, wn = wid & 1;

    // global load assignment: thread owns one (row, 8-col half) of each tile
    int arow  = tid >> 1;            // 0..127
    int halfc = (tid & 1) * 8;
    int slot  = mt * 128 + arow;
    const float* aptr = nullptr;
    if (slot < cnt) {
        int tok = g_tok[e * T_TOK + slot];
        aptr = x + (size_t)tok * H_DIM + halfc;
    }
    int jj = arow >> 1, s = arow & 1;
    const float* bptr = w13 + ((size_t)e * 2 * I_DIM + (s ? I_DIM : 0) +
                               (size_t)nt * 64 + jj) * H_DIM + halfc;

    float acc[2][8][4];
#pragma unroll
    for (int i = 0; i < 2; i++)
#pragma unroll
        for (int j = 0; j < 8; j++)
#pragma unroll
            for (int c = 0; c < 4; c++) acc[i][j][c] = 0.0f;

    int sb = arow * 20 + halfc;
    for (int kb = 0; kb < H_DIM / 16; kb++) {
        int k0 = kb * 16;
        float4 av0 = make_float4(0, 0, 0, 0), av1 = make_float4(0, 0, 0, 0);
        if (aptr) {
            av0 = *(const float4*)(aptr + k0);
            av1 = *(const float4*)(aptr + k0 + 4);
        }
        float4 bv0 = *(const float4*)(bptr + k0);
        float4 bv1 = *(const float4*)(bptr + k0 + 4);
        __syncthreads();
        As[sb + 0] = tf32r(av0.x); As[sb + 1] = tf32r(av0.y);
        As[sb + 2] = tf32r(av0.z); As[sb + 3] = tf32r(av0.w);
        As[sb + 4] = tf32r(av1.x); As[sb + 5] = tf32r(av1.y);
        As[sb + 6] = tf32r(av1.z); As[sb + 7] = tf32r(av1.w);
        Bs[sb + 0] = tf32r(bv0.x); Bs[sb + 1] = tf32r(bv0.y);
        Bs[sb + 2] = tf32r(bv0.z); Bs[sb + 3] = tf32r(bv0.w);
        Bs[sb + 4] = tf32r(bv1.x); Bs[sb + 5] = tf32r(bv1.y);
        Bs[sb + 6] = tf32r(bv1.z); Bs[sb + 7] = tf32r(bv1.w);
        __syncthreads();

        const uint32_t* Au = (const uint32_t*)As;
        const uint32_t* Bu = (const uint32_t*)Bs;
        int lr = lane >> 2, lc = lane & 3;
#pragma unroll
        for (int kst = 0; kst < 2; kst++) {
            int kc = kst * 8 + lc;
            uint32_t a[2][4], b[8][2];
#pragma unroll
            for (int m2 = 0; m2 < 2; m2++) {
                int r = wm * 32 + m2 * 16 + lr;
                a[m2][0] = Au[r * 20 + kc];
                a[m2][1] = Au[(r + 8) * 20 + kc];
                a[m2][2] = Au[r * 20 + kc + 4];
                a[m2][3] = Au[(r + 8) * 20 + kc + 4];
            }
#pragma unroll
            for (int n8 = 0; n8 < 8; n8++) {
                int c = wn * 64 + n8 * 8 + lr;
                b[n8][0] = Bu[c * 20 + kc];
                b[n8][1] = Bu[c * 20 + kc + 4];
            }
#pragma unroll
            for (int m2 = 0; m2 < 2; m2++)
#pragma unroll
                for (int n8 = 0; n8 < 8; n8++) mma_tf32(acc[m2][n8], a[m2], b[n8]);
        }
    }

    // epilogue: h = silu(gate) * up
    int lr = lane >> 2, q = lane & 3;
#pragma unroll
    for (int m2 = 0; m2 < 2; m2++) {
        int r0 = wm * 32 + m2 * 16 + lr;
        int slot0 = mt * 128 + r0;
        int slot1 = slot0 + 8;
#pragma unroll
        for (int n8 = 0; n8 < 8; n8++) {
            int hcol = nt * 64 + wn * 32 + n8 * 4 + q;
            if (slot0 < cnt) {
                float g = acc[m2][n8][0], u = acc[m2][n8][1];
                g_h[(size_t)(rowb + slot0) * I_DIM + hcol] = g / (1.0f + expf(-g)) * u;
            }
            if (slot1 < cnt) {
                float g = acc[m2][n8][2], u = acc[m2][n8][3];
                g_h[(size_t)(rowb + slot1) * I_DIM + hcol] = g / (1.0f + expf(-g)) * u;
            }
        }
    }
}

// ---------------- phase 4: GEMM2  out += wgt * (h W2^T) ----------------
__global__ __launch_bounds__(256) void gemm2_kernel(const float* __restrict__ w2,
                                                    float* __restrict__ out) {
    __shared__ float As[128 * 20];
    __shared__ float Bs[128 * 20];

    int bid = blockIdx.x;
    if (bid >= g_cum2[E_NUM]) return;
    int e = 0;
#pragma unroll
    for (int k = 0; k < E_NUM; k++) if (bid >= g_cum2[k + 1]) e = k + 1;
    int local = bid - g_cum2[e];
    int mt = local >> 3, nt = local & 7;   // nt fastest -> L2 reuse of h tile
    int cnt  = g_cnt[e];
    int rowb = g_rowbase[e];

    int tid  = threadIdx.x;
    int lane = tid & 31, wid = tid >> 5;
    int wm = wid >> 1, wn = wid & 1;

    int arow  = tid >> 1;
    int halfc = (tid & 1) * 8;
    int slot  = mt * 128 + arow;
    const float* aptr = (slot < cnt)
        ? g_h + (size_t)(rowb + slot) * I_DIM + halfc : nullptr;
    const float* bptr = w2 + ((size_t)e * H_DIM + nt * 128 + arow) * I_DIM + halfc;

    float acc[2][8][4];
#pragma unroll
    for (int i = 0; i < 2; i++)
#pragma unroll
        for (int j = 0; j < 8; j++)
#pragma unroll
            for (int c = 0; c < 4; c++) acc[i][j][c] = 0.0f;

    int sb = arow * 20 + halfc;
    for (int kb = 0; kb < I_DIM / 16; kb++) {
        int k0 = kb * 16;
        float4 av0 = make_float4(0, 0, 0, 0), av1 = make_float4(0, 0, 0, 0);
        if (aptr) {
            av0 = *(const float4*)(aptr + k0);
            av1 = *(const float4*)(aptr + k0 + 4);
        }
        float4 bv0 = *(const float4*)(bptr + k0);
        float4 bv1 = *(const float4*)(bptr + k0 + 4);
        __syncthreads();
        As[sb + 0] = tf32r(av0.x); As[sb + 1] = tf32r(av0.y);
        As[sb + 2] = tf32r(av0.z); As[sb + 3] = tf32r(av0.w);
        As[sb + 4] = tf32r(av1.x); As[sb + 5] = tf32r(av1.y);
        As[sb + 6] = tf32r(av1.z); As[sb + 7] = tf32r(av1.w);
        Bs[sb + 0] = tf32r(bv0.x); Bs[sb + 1] = tf32r(bv0.y);
        Bs[sb + 2] = tf32r(bv0.z); Bs[sb + 3] = tf32r(bv0.w);
        Bs[sb + 4] = tf32r(bv1.x); Bs[sb + 5] = tf32r(bv1.y);
        Bs[sb + 6] = tf32r(bv1.z); Bs[sb + 7] = tf32r(bv1.w);
        __syncthreads();

        const uint32_t* Au = (const uint32_t*)As;
        const uint32_t* Bu = (const uint32_t*)Bs;
        int lr = lane >> 2, lc = lane & 3;
#pragma unroll
        for (int kst = 0; kst < 2; kst++) {
            int kc = kst * 8 + lc;
            uint32_t a[2][4], b[8][2];
#pragma unroll
            for (int m2 = 0; m2 < 2; m2++) {
                int r = wm * 32 + m2 * 16 + lr;
                a[m2][0] = Au[r * 20 + kc];
                a[m2][1] = Au[(r + 8) * 20 + kc];
                a[m2][2] = Au[r * 20 + kc + 4];
                a[m2][3] = Au[(r + 8) * 20 + kc + 4];
            }
#pragma unroll
            for (int n8 = 0; n8 < 8; n8++) {
                int c = wn * 64 + n8 * 8 + lr;
                b[n8][0] = Bu[c * 20 + kc];
                b[n8][1] = Bu[c * 20 + kc + 4];
            }
#pragma unroll
            for (int m2 = 0; m2 < 2; m2++)
#pragma unroll
                for (int n8 = 0; n8 < 8; n8++) mma_tf32(acc[m2][n8], a[m2], b[n8]);
        }
    }

    // epilogue: weighted atomic combine (each out element gets exactly 2 adds)
    int lr = lane >> 2, q = lane & 3;
#pragma unroll
    for (int m2 = 0; m2 < 2; m2++) {
        int slot0 = mt * 128 + wm * 32 + m2 * 16 + lr;
        int slot1 = slot0 + 8;
        int   tok0 = 0, tok1 = 0;
        float wt0 = 0.0f, wt1 = 0.0f;
        if (slot0 < cnt) { tok0 = g_tok[e * T_TOK + slot0]; wt0 = g_wt[e * T_TOK + slot0]; }
        if (slot1 < cnt) { tok1 = g_tok[e * T_TOK + slot1]; wt1 = g_wt[e * T_TOK + slot1]; }
#pragma unroll
        for (int n8 = 0; n8 < 8; n8++) {
            int col = nt * 128 + wn * 64 + n8 * 8 + q * 2;
            if (slot0 < cnt) {
                atomicAdd(out + (size_t)tok0 * H_DIM + col,     acc[m2][n8][0] * wt0);
                atomicAdd(out + (size_t)tok0 * H_DIM + col + 1, acc[m2][n8][1] * wt0);
            }
            if (slot1 < cnt) {
                atomicAdd(out + (size_t)tok1 * H_DIM + col,     acc[m2][n8][2] * wt1);
                atomicAdd(out + (size_t)tok1 * H_DIM + col + 1, acc[m2][n8][3] * wt1);
            }
        }
    }
}

// ---------------- launch ----------------
extern "C" void kernel_launch(void* const* d_in, const int* in_sizes, int n_in,
                              void* d_out, int out_size) {
    const float* x      = (const float*)d_in[0];
    const float* logits = (const float*)d_in[1];
    const float* w13    = (const float*)d_in[2];
    const float* w2     = (const float*)d_in[3];
    float* out = (float*)d_out;

    cudaMemsetAsync(out, 0, (size_t)T_TOK * H_DIM * sizeof(float));
    init_kernel<<<1, 32>>>();
    router_kernel<<<T_TOK / 256, 256>>>(logits);
    sched_kernel<<<1, 1>>>();
    gemm1_kernel<<<GRID1, 256>>>(x, w13);
    gemm2_kernel<<<GRID2, 256>>>(w2, out);
}